// round 1
// baseline (speedup 1.0000x reference)
#include <cuda_runtime.h>
#include <math.h>

// Problem dims (fixed by setup_inputs): x [4,4096,2048] fp32, W [2048,2048] fp32
#define M_DIM 16384
#define K_DIM 2048
#define N_DIM 2048

static const long long NELEM = (long long)M_DIM * (long long)K_DIM;

// Scratch: pruned activations (2:4) in fp32. __device__ global (no alloc allowed).
__device__ float g_xsp[M_DIM * K_DIM];
// Moment accumulators: sum_x, sumsq_x, sum_sp, sumsq_sp
__device__ double g_sums[4];
// Variance-correction scalar
__device__ float g_v;

// ---------------------------------------------------------------------------
// Kernel 0: reset accumulators (graph replays reuse device globals)
// ---------------------------------------------------------------------------
__global__ void zero_sums_kernel() {
    if (threadIdx.x < 4) g_sums[threadIdx.x] = 0.0;
}

// ---------------------------------------------------------------------------
// Kernel 1: 2:4 prune (keep top-2 |.| per contiguous group of 4, ties -> lower
// index kept, matching jax top_k) + moment accumulation.
// ---------------------------------------------------------------------------
__global__ void prune_kernel(const float* __restrict__ x) {
    const long long ng = NELEM / 4;
    const float4* __restrict__ x4 = (const float4*)x;
    float4* __restrict__ y4 = (float4*)g_xsp;

    float s0 = 0.f, s1 = 0.f, s2 = 0.f, s3 = 0.f;

    const long long stride = (long long)gridDim.x * blockDim.x;
    for (long long g = (long long)blockIdx.x * blockDim.x + threadIdx.x;
         g < ng; g += stride) {
        float4 v = x4[g];
        float e[4] = {v.x, v.y, v.z, v.w};
        float a[4] = {fabsf(v.x), fabsf(v.y), fabsf(v.z), fabsf(v.w)};
        float o[4];
#pragma unroll
        for (int i = 0; i < 4; i++) {
            int beats = 0;
#pragma unroll
            for (int j = 0; j < 4; j++) {
                if (j == i) continue;
                // j beats i if strictly larger abs, or equal abs with lower index
                beats += (a[j] > a[i]) || (a[j] == a[i] && j < i);
            }
            o[i] = (beats < 2) ? e[i] : 0.f;
        }
        s0 += e[0] + e[1] + e[2] + e[3];
        s1 += e[0]*e[0] + e[1]*e[1] + e[2]*e[2] + e[3]*e[3];
        s2 += o[0] + o[1] + o[2] + o[3];
        s3 += o[0]*o[0] + o[1]*o[1] + o[2]*o[2] + o[3]*o[3];
        y4[g] = make_float4(o[0], o[1], o[2], o[3]);
    }

    // warp reduce
#pragma unroll
    for (int off = 16; off > 0; off >>= 1) {
        s0 += __shfl_down_sync(0xffffffffu, s0, off);
        s1 += __shfl_down_sync(0xffffffffu, s1, off);
        s2 += __shfl_down_sync(0xffffffffu, s2, off);
        s3 += __shfl_down_sync(0xffffffffu, s3, off);
    }
    __shared__ float red[4][8];
    int lane = threadIdx.x & 31;
    int w = threadIdx.x >> 5;
    if (lane == 0) {
        red[0][w] = s0; red[1][w] = s1; red[2][w] = s2; red[3][w] = s3;
    }
    __syncthreads();
    if (threadIdx.x == 0) {
        float t0 = 0.f, t1 = 0.f, t2 = 0.f, t3 = 0.f;
        int nw = (blockDim.x + 31) >> 5;
        for (int i = 0; i < nw; i++) {
            t0 += red[0][i]; t1 += red[1][i]; t2 += red[2][i]; t3 += red[3][i];
        }
        atomicAdd(&g_sums[0], (double)t0);
        atomicAdd(&g_sums[1], (double)t1);
        atomicAdd(&g_sums[2], (double)t2);
        atomicAdd(&g_sums[3], (double)t3);
    }
}

// ---------------------------------------------------------------------------
// Kernel 2: v = sqrt(var(x) / max(var(x_sp), 1e-9)), ddof=1
// ---------------------------------------------------------------------------
__global__ void compute_v_kernel() {
    double n = (double)NELEM;
    double var_x  = (g_sums[1] - g_sums[0] * g_sums[0] / n) / (n - 1.0);
    double var_sp = (g_sums[3] - g_sums[2] * g_sums[2] / n) / (n - 1.0);
    double denom = var_sp > 1e-9 ? var_sp : 1e-9;
    g_v = (float)sqrt(var_x / denom);
}

// ---------------------------------------------------------------------------
// Kernel 3: SGEMM  out[m][n] = v * sum_k x_sp[m][k] * W[n][k]
// NT layout (both K-major). BM=BN=128, BK=16, 8x8 per thread, 256 threads.
// ---------------------------------------------------------------------------
#define BM 128
#define BN 128
#define BK 16
#define TM 8
#define TN 8

__global__ __launch_bounds__(256, 2)
void sgemm_kernel(const float* __restrict__ W, float* __restrict__ out) {
    __shared__ float As[BK][BM + 4];
    __shared__ float Bs[BK][BN + 4];

    const float* __restrict__ A = g_xsp;

    const int bm = blockIdx.y * BM;
    const int bn = blockIdx.x * BN;
    const int tid = threadIdx.x;

    const int tx = tid & 15;  // thread column within 16x16 thread grid (N dir)
    const int ty = tid >> 4;  // thread row (M dir)

    // load mapping: 128 rows x 4 float4 per row per tile; 256 threads -> 2 rows each
    const int lr = tid >> 2;       // 0..63
    const int lc = tid & 3;        // float4 index 0..3 (within BK=16)

    float acc[TM][TN];
#pragma unroll
    for (int i = 0; i < TM; i++)
#pragma unroll
        for (int j = 0; j < TN; j++) acc[i][j] = 0.f;

    for (int k0 = 0; k0 < K_DIM; k0 += BK) {
#pragma unroll
        for (int r = 0; r < 2; r++) {
            const int row = lr + r * 64;
            const float4 va = *(const float4*)&A[(long long)(bm + row) * K_DIM + k0 + lc * 4];
            As[lc * 4 + 0][row] = va.x;
            As[lc * 4 + 1][row] = va.y;
            As[lc * 4 + 2][row] = va.z;
            As[lc * 4 + 3][row] = va.w;
            const float4 vb = *(const float4*)&W[(long long)(bn + row) * K_DIM + k0 + lc * 4];
            Bs[lc * 4 + 0][row] = vb.x;
            Bs[lc * 4 + 1][row] = vb.y;
            Bs[lc * 4 + 2][row] = vb.z;
            Bs[lc * 4 + 3][row] = vb.w;
        }
        __syncthreads();

#pragma unroll
        for (int kk = 0; kk < BK; kk++) {
            float af[TM], bf[TN];
#pragma unroll
            for (int i = 0; i < TM; i++) af[i] = As[kk][ty * TM + i];
#pragma unroll
            for (int j = 0; j < TN; j++) bf[j] = Bs[kk][tx * TN + j];
#pragma unroll
            for (int i = 0; i < TM; i++)
#pragma unroll
                for (int j = 0; j < TN; j++)
                    acc[i][j] = fmaf(af[i], bf[j], acc[i][j]);
        }
        __syncthreads();
    }

    const float v = g_v;
#pragma unroll
    for (int i = 0; i < TM; i++) {
        const long long orow = (long long)(bm + ty * TM + i) * N_DIM + bn + tx * TN;
        float4 o0 = make_float4(v * acc[i][0], v * acc[i][1], v * acc[i][2], v * acc[i][3]);
        float4 o1 = make_float4(v * acc[i][4], v * acc[i][5], v * acc[i][6], v * acc[i][7]);
        *(float4*)&out[orow + 0] = o0;
        *(float4*)&out[orow + 4] = o1;
    }
}

// ---------------------------------------------------------------------------
// Entry point
// ---------------------------------------------------------------------------
extern "C" void kernel_launch(void* const* d_in, const int* in_sizes, int n_in,
                              void* d_out, int out_size) {
    const float* x = (const float*)d_in[0];
    const float* w = (const float*)d_in[1];
    float* out = (float*)d_out;

    zero_sums_kernel<<<1, 4>>>();
    prune_kernel<<<2048, 256>>>(x);
    compute_v_kernel<<<1, 1>>>();

    dim3 grid(N_DIM / BN, M_DIM / BM);
    sgemm_kernel<<<grid, 256>>>(w, out);
}

// round 3
// speedup vs baseline: 4.8890x; 4.8890x over previous
#include <cuda_runtime.h>
#include <math.h>
#include <stdint.h>

// Problem dims (fixed by setup_inputs): x [4,4096,2048] fp32, W [2048,2048] fp32
#define M_DIM 16384
#define K_DIM 2048
#define N_DIM 2048

static const long long NELEM = (long long)M_DIM * (long long)K_DIM;

// Scratch: pruned activations (2:4) in fp32. __device__ global (no alloc allowed).
__device__ float g_xsp[M_DIM * K_DIM];
__device__ double g_sums[4];
__device__ float g_v;

// ---------------------------------------------------------------------------
// Kernel 0: reset accumulators
// ---------------------------------------------------------------------------
__global__ void zero_sums_kernel() {
    if (threadIdx.x < 4) g_sums[threadIdx.x] = 0.0;
}

// ---------------------------------------------------------------------------
// Kernel 1: 2:4 prune + moment accumulation
// ---------------------------------------------------------------------------
__global__ void prune_kernel(const float* __restrict__ x) {
    const long long ng = NELEM / 4;
    const float4* __restrict__ x4 = (const float4*)x;
    float4* __restrict__ y4 = (float4*)g_xsp;

    float s0 = 0.f, s1 = 0.f, s2 = 0.f, s3 = 0.f;

    const long long stride = (long long)gridDim.x * blockDim.x;
    for (long long g = (long long)blockIdx.x * blockDim.x + threadIdx.x;
         g < ng; g += stride) {
        float4 v = x4[g];
        float e[4] = {v.x, v.y, v.z, v.w};
        float a[4] = {fabsf(v.x), fabsf(v.y), fabsf(v.z), fabsf(v.w)};
        float o[4];
#pragma unroll
        for (int i = 0; i < 4; i++) {
            int beats = 0;
#pragma unroll
            for (int j = 0; j < 4; j++) {
                if (j == i) continue;
                beats += (a[j] > a[i]) || (a[j] == a[i] && j < i);
            }
            o[i] = (beats < 2) ? e[i] : 0.f;
        }
        s0 += e[0] + e[1] + e[2] + e[3];
        s1 += e[0]*e[0] + e[1]*e[1] + e[2]*e[2] + e[3]*e[3];
        s2 += o[0] + o[1] + o[2] + o[3];
        s3 += o[0]*o[0] + o[1]*o[1] + o[2]*o[2] + o[3]*o[3];
        y4[g] = make_float4(o[0], o[1], o[2], o[3]);
    }

#pragma unroll
    for (int off = 16; off > 0; off >>= 1) {
        s0 += __shfl_down_sync(0xffffffffu, s0, off);
        s1 += __shfl_down_sync(0xffffffffu, s1, off);
        s2 += __shfl_down_sync(0xffffffffu, s2, off);
        s3 += __shfl_down_sync(0xffffffffu, s3, off);
    }
    __shared__ float red[4][8];
    int lane = threadIdx.x & 31;
    int w = threadIdx.x >> 5;
    if (lane == 0) {
        red[0][w] = s0; red[1][w] = s1; red[2][w] = s2; red[3][w] = s3;
    }
    __syncthreads();
    if (threadIdx.x == 0) {
        float t0 = 0.f, t1 = 0.f, t2 = 0.f, t3 = 0.f;
        int nw = (blockDim.x + 31) >> 5;
        for (int i = 0; i < nw; i++) {
            t0 += red[0][i]; t1 += red[1][i]; t2 += red[2][i]; t3 += red[3][i];
        }
        atomicAdd(&g_sums[0], (double)t0);
        atomicAdd(&g_sums[1], (double)t1);
        atomicAdd(&g_sums[2], (double)t2);
        atomicAdd(&g_sums[3], (double)t3);
    }
}

// ---------------------------------------------------------------------------
// Kernel 2: v = sqrt(var(x) / max(var(x_sp), 1e-9)), ddof=1
// ---------------------------------------------------------------------------
__global__ void compute_v_kernel() {
    double n = (double)NELEM;
    double var_x  = (g_sums[1] - g_sums[0] * g_sums[0] / n) / (n - 1.0);
    double var_sp = (g_sums[3] - g_sums[2] * g_sums[2] / n) / (n - 1.0);
    double denom = var_sp > 1e-9 ? var_sp : 1e-9;
    g_v = (float)sqrt(var_x / denom);
}

// ---------------------------------------------------------------------------
// Kernel 3: tf32 mma.sync GEMM  out[m][n] = v * sum_k x_sp[m][k] * W[n][k]
// BM=128 BN=128 BK=32, 3-stage cp.async, 8 warps (2x4), warp tile 64x32.
// ---------------------------------------------------------------------------
#define BM 128
#define BN 128
#define BK 32
#define STAGES 3
#define NITER (K_DIM / BK)              // 64

#define LDK (BK + 4)                    // padded row stride in floats (36)
#define A_STG_F (BM * LDK)              // 4608 floats
#define B_STG_F (BN * LDK)              // 4608 floats
#define STG_F (A_STG_F + B_STG_F)       // 9216 floats
#define SMEM_DYN (STAGES * STG_F * 4)   // 110592 bytes

static __device__ __forceinline__ uint32_t smem_u32(const void* p) {
    uint32_t a;
    asm("{ .reg .u64 t; cvta.to.shared.u64 t, %1; cvt.u32.u64 %0, t; }" : "=r"(a) : "l"(p));
    return a;
}

static __device__ __forceinline__ uint32_t to_tf32(float x) {
    uint32_t r;
    asm("cvt.rna.tf32.f32 %0, %1;" : "=r"(r) : "f"(x));
    return r;
}

#define CP_ASYNC16(dst, src) \
    asm volatile("cp.async.cg.shared.global [%0], [%1], 16;" :: "r"(dst), "l"(src) : "memory")
#define CP_COMMIT() asm volatile("cp.async.commit_group;" ::: "memory")
#define CP_WAIT1()  asm volatile("cp.async.wait_group 1;" ::: "memory")

static __device__ __forceinline__ void mma_tf32(
    float* c, const uint32_t* a, const uint32_t* b) {
    asm volatile(
        "mma.sync.aligned.m16n8k8.row.col.f32.tf32.tf32.f32 "
        "{%0, %1, %2, %3}, {%4, %5, %6, %7}, {%8, %9}, {%0, %1, %2, %3};"
        : "+f"(c[0]), "+f"(c[1]), "+f"(c[2]), "+f"(c[3])
        : "r"(a[0]), "r"(a[1]), "r"(a[2]), "r"(a[3]), "r"(b[0]), "r"(b[1]));
}

__global__ __launch_bounds__(256)
void gemm_tf32_kernel(const float* __restrict__ W, float* __restrict__ out) {
    extern __shared__ float smem[];

    const int tid = threadIdx.x;
    const int wid = tid >> 5;
    const int lane = tid & 31;
    const int bm = blockIdx.y * BM;
    const int bn = blockIdx.x * BN;

    const uint32_t smem_b = smem_u32(smem);
    const char* a_gm = (const char*)g_xsp + (size_t)bm * (K_DIM * 4);
    const char* b_gm = (const char*)W + (size_t)bn * (K_DIM * 4);

    // ---- async loader: stage buf <- ktile kt --------------------------------
    auto load_stage = [&](int buf, int kt) {
        const uint32_t sA = smem_b + buf * (STG_F * 4);
        const uint32_t sB = sA + A_STG_F * 4;
        const int kb = kt * (BK * 4);           // byte offset along K
#pragma unroll
        for (int i = 0; i < 4; i++) {
            const int ch = tid + i * 256;       // 0..1023
            const int row = ch >> 3, col = ch & 7;
            CP_ASYNC16(sA + row * (LDK * 4) + col * 16,
                       a_gm + (size_t)row * (K_DIM * 4) + kb + col * 16);
            CP_ASYNC16(sB + row * (LDK * 4) + col * 16,
                       b_gm + (size_t)row * (K_DIM * 4) + kb + col * 16);
        }
    };

    // prologue: preload STAGES-1 ktiles
#pragma unroll
    for (int s = 0; s < STAGES - 1; s++) {
        load_stage(s, s);
        CP_COMMIT();
    }

    const int mw = (wid >> 2) * 64;     // warp M offset in tile
    const int nw = (wid & 3) * 32;      // warp N offset in tile
    const int gr = lane >> 2;           // group row 0..7
    const int tg = lane & 3;            // thread-in-group 0..3

    float acc[4][4][4];
#pragma unroll
    for (int i = 0; i < 4; i++)
#pragma unroll
        for (int j = 0; j < 4; j++)
#pragma unroll
            for (int q = 0; q < 4; q++) acc[i][j][q] = 0.f;

    for (int kt = 0; kt < NITER; kt++) {
        CP_WAIT1();
        __syncthreads();

        const int next = kt + STAGES - 1;
        if (next < NITER) load_stage(next % STAGES, next);
        CP_COMMIT();

        const float* As = smem + (kt % STAGES) * STG_F;
        const float* Bs = As + A_STG_F;

#pragma unroll
        for (int kk = 0; kk < BK; kk += 8) {
            uint32_t af[4][4];
#pragma unroll
            for (int fm = 0; fm < 4; fm++) {
                const int r = mw + fm * 16 + gr;
                af[fm][0] = to_tf32(As[r * LDK + kk + tg]);
                af[fm][1] = to_tf32(As[(r + 8) * LDK + kk + tg]);
                af[fm][2] = to_tf32(As[r * LDK + kk + tg + 4]);
                af[fm][3] = to_tf32(As[(r + 8) * LDK + kk + tg + 4]);
            }
            uint32_t bf[4][2];
#pragma unroll
            for (int fn = 0; fn < 4; fn++) {
                const int n = nw + fn * 8 + gr;
                bf[fn][0] = to_tf32(Bs[n * LDK + kk + tg]);
                bf[fn][1] = to_tf32(Bs[n * LDK + kk + tg + 4]);
            }
#pragma unroll
            for (int fm = 0; fm < 4; fm++)
#pragma unroll
                for (int fn = 0; fn < 4; fn++)
                    mma_tf32(acc[fm][fn], af[fm], bf[fn]);
        }
        __syncthreads();
    }

    // ---- epilogue -----------------------------------------------------------
    const float v = g_v;
#pragma unroll
    for (int fm = 0; fm < 4; fm++) {
        const int r0 = bm + mw + fm * 16 + gr;
        const int r1 = r0 + 8;
#pragma unroll
        for (int fn = 0; fn < 4; fn++) {
            const int c = bn + nw + fn * 8 + tg * 2;
            *(float2*)&out[(size_t)r0 * N_DIM + c] =
                make_float2(v * acc[fm][fn][0], v * acc[fm][fn][1]);
            *(float2*)&out[(size_t)r1 * N_DIM + c] =
                make_float2(v * acc[fm][fn][2], v * acc[fm][fn][3]);
        }
    }
}

// ---------------------------------------------------------------------------
// Entry point
// ---------------------------------------------------------------------------
extern "C" void kernel_launch(void* const* d_in, const int* in_sizes, int n_in,
                              void* d_out, int out_size) {
    const float* x = (const float*)d_in[0];
    const float* w = (const float*)d_in[1];
    float* out = (float*)d_out;

    zero_sums_kernel<<<1, 4>>>();
    prune_kernel<<<2048, 256>>>(x);
    compute_v_kernel<<<1, 1>>>();

    cudaFuncSetAttribute(gemm_tf32_kernel,
                         cudaFuncAttributeMaxDynamicSharedMemorySize, SMEM_DYN);
    dim3 grid(N_DIM / BN, M_DIM / BM);
    gemm_tf32_kernel<<<grid, 256, SMEM_DYN>>>(w, out);
}

// round 4
// speedup vs baseline: 12.9842x; 2.6558x over previous
#include <cuda_runtime.h>
#include <cuda_fp16.h>
#include <math.h>
#include <stdint.h>

// Problem dims (fixed by setup_inputs): x [4,4096,2048] fp32, W [2048,2048] fp32
#define M_DIM 16384
#define K_DIM 2048
#define N_DIM 2048

static const long long NELEM = (long long)M_DIM * (long long)K_DIM;

// Scratch (no alloc allowed): pruned activations and weights in fp16.
__device__ __half g_xsp[M_DIM * K_DIM];   // 64 MB
__device__ __half g_wh[N_DIM * K_DIM];    // 8 MB
__device__ double g_sums[4];
__device__ float g_v;

// ---------------------------------------------------------------------------
// Kernel 0: reset accumulators
// ---------------------------------------------------------------------------
__global__ void zero_sums_kernel() {
    if (threadIdx.x < 4) g_sums[threadIdx.x] = 0.0;
}

// ---------------------------------------------------------------------------
// Kernel 1: 2:4 prune + moment accumulation; writes half output
// ---------------------------------------------------------------------------
__global__ void prune_kernel(const float* __restrict__ x) {
    const long long ng = NELEM / 4;
    const float4* __restrict__ x4 = (const float4*)x;
    __half2* __restrict__ y2 = (__half2*)g_xsp;

    float s0 = 0.f, s1 = 0.f, s2 = 0.f, s3 = 0.f;

    const long long stride = (long long)gridDim.x * blockDim.x;
    for (long long g = (long long)blockIdx.x * blockDim.x + threadIdx.x;
         g < ng; g += stride) {
        float4 v = x4[g];
        float e[4] = {v.x, v.y, v.z, v.w};
        float a[4] = {fabsf(v.x), fabsf(v.y), fabsf(v.z), fabsf(v.w)};
        float o[4];
#pragma unroll
        for (int i = 0; i < 4; i++) {
            int beats = 0;
#pragma unroll
            for (int j = 0; j < 4; j++) {
                if (j == i) continue;
                beats += (a[j] > a[i]) || (a[j] == a[i] && j < i);
            }
            o[i] = (beats < 2) ? e[i] : 0.f;
        }
        s0 += e[0] + e[1] + e[2] + e[3];
        s1 += e[0]*e[0] + e[1]*e[1] + e[2]*e[2] + e[3]*e[3];
        s2 += o[0] + o[1] + o[2] + o[3];
        s3 += o[0]*o[0] + o[1]*o[1] + o[2]*o[2] + o[3]*o[3];
        y2[2 * g]     = __floats2half2_rn(o[0], o[1]);
        y2[2 * g + 1] = __floats2half2_rn(o[2], o[3]);
    }

#pragma unroll
    for (int off = 16; off > 0; off >>= 1) {
        s0 += __shfl_down_sync(0xffffffffu, s0, off);
        s1 += __shfl_down_sync(0xffffffffu, s1, off);
        s2 += __shfl_down_sync(0xffffffffu, s2, off);
        s3 += __shfl_down_sync(0xffffffffu, s3, off);
    }
    __shared__ float red[4][8];
    int lane = threadIdx.x & 31;
    int w = threadIdx.x >> 5;
    if (lane == 0) {
        red[0][w] = s0; red[1][w] = s1; red[2][w] = s2; red[3][w] = s3;
    }
    __syncthreads();
    if (threadIdx.x == 0) {
        float t0 = 0.f, t1 = 0.f, t2 = 0.f, t3 = 0.f;
        int nw = (blockDim.x + 31) >> 5;
        for (int i = 0; i < nw; i++) {
            t0 += red[0][i]; t1 += red[1][i]; t2 += red[2][i]; t3 += red[3][i];
        }
        atomicAdd(&g_sums[0], (double)t0);
        atomicAdd(&g_sums[1], (double)t1);
        atomicAdd(&g_sums[2], (double)t2);
        atomicAdd(&g_sums[3], (double)t3);
    }
}

// ---------------------------------------------------------------------------
// Kernel 1b: convert W to fp16
// ---------------------------------------------------------------------------
__global__ void wconv_kernel(const float* __restrict__ W) {
    const int i = blockIdx.x * blockDim.x + threadIdx.x;  // over NK/4
    float4 w4 = ((const float4*)W)[i];
    __half2* y = (__half2*)g_wh;
    y[2 * i]     = __floats2half2_rn(w4.x, w4.y);
    y[2 * i + 1] = __floats2half2_rn(w4.z, w4.w);
}

// ---------------------------------------------------------------------------
// Kernel 2: v = sqrt(var(x) / max(var(x_sp), 1e-9)), ddof=1
// ---------------------------------------------------------------------------
__global__ void compute_v_kernel() {
    double n = (double)NELEM;
    double var_x  = (g_sums[1] - g_sums[0] * g_sums[0] / n) / (n - 1.0);
    double var_sp = (g_sums[3] - g_sums[2] * g_sums[2] / n) / (n - 1.0);
    double denom = var_sp > 1e-9 ? var_sp : 1e-9;
    g_v = (float)sqrt(var_x / denom);
}

// ---------------------------------------------------------------------------
// Kernel 3: fp16 mma.sync GEMM  out[m][n] = v * sum_k x_sp[m][k] * W[n][k]
// BM=128 BN=128 BK=64(halves), 3-stage cp.async ring, SW128 swizzle,
// ldmatrix fragment loads. 8 warps (2x4), warp tile 64x32.
// ---------------------------------------------------------------------------
#define BM 128
#define BN 128
#define BK 64                         // halves per K tile (128 bytes/row)
#define STAGES 3
#define NITER (K_DIM / BK)            // 32

#define A_STG_B (BM * 128)            // 16 KB
#define B_STG_B (BN * 128)            // 16 KB
#define STG_B (A_STG_B + B_STG_B)     // 32 KB
#define SMEM_DYN (STAGES * STG_B)     // 96 KB

static __device__ __forceinline__ uint32_t smem_u32(const void* p) {
    uint32_t a;
    asm("{ .reg .u64 t; cvta.to.shared.u64 t, %1; cvt.u32.u64 %0, t; }" : "=r"(a) : "l"(p));
    return a;
}

#define CP_ASYNC16(dst, src) \
    asm volatile("cp.async.cg.shared.global [%0], [%1], 16;" :: "r"(dst), "l"(src) : "memory")
#define CP_COMMIT() asm volatile("cp.async.commit_group;" ::: "memory")
#define CP_WAIT1()  asm volatile("cp.async.wait_group 1;" ::: "memory")

#define LDSM_X4(r0, r1, r2, r3, addr) \
    asm volatile("ldmatrix.sync.aligned.m8n8.x4.shared.b16 {%0,%1,%2,%3}, [%4];" \
        : "=r"(r0), "=r"(r1), "=r"(r2), "=r"(r3) : "r"(addr))

static __device__ __forceinline__ void mma_f16(
    float* c, const uint32_t* a, const uint32_t* b) {
    asm volatile(
        "mma.sync.aligned.m16n8k16.row.col.f32.f16.f16.f32 "
        "{%0, %1, %2, %3}, {%4, %5, %6, %7}, {%8, %9}, {%0, %1, %2, %3};"
        : "+f"(c[0]), "+f"(c[1]), "+f"(c[2]), "+f"(c[3])
        : "r"(a[0]), "r"(a[1]), "r"(a[2]), "r"(a[3]), "r"(b[0]), "r"(b[1]));
}

__global__ __launch_bounds__(256, 2)
void gemm_f16_kernel(float* __restrict__ out) {
    extern __shared__ char smem[];

    const int tid = threadIdx.x;
    const int wid = tid >> 5;
    const int lane = tid & 31;
    const int bm = blockIdx.y * BM;
    const int bn = blockIdx.x * BN;

    const uint32_t smem_b = smem_u32(smem);
    const char* a_gm = (const char*)g_xsp + (size_t)bm * (K_DIM * 2);
    const char* b_gm = (const char*)g_wh + (size_t)bn * (K_DIM * 2);

    // ---- async loader: stage buf <- ktile kt (SW128 chunk^row swizzle) ------
    auto load_stage = [&](int buf, int kt) {
        const uint32_t sA = smem_b + buf * STG_B;
        const uint32_t sB = sA + A_STG_B;
        const int kb = kt * 128;                // byte offset along K
#pragma unroll
        for (int i = 0; i < 4; i++) {
            const int ch = tid + i * 256;       // 0..1023
            const int row = ch >> 3, c = ch & 7;
            const uint32_t sw = ((uint32_t)(c ^ (row & 7))) << 4;
            CP_ASYNC16(sA + row * 128 + sw,
                       a_gm + (size_t)row * (K_DIM * 2) + kb + c * 16);
            CP_ASYNC16(sB + row * 128 + sw,
                       b_gm + (size_t)row * (K_DIM * 2) + kb + c * 16);
        }
    };

#pragma unroll
    for (int s = 0; s < STAGES - 1; s++) {
        load_stage(s, s);
        CP_COMMIT();
    }

    const int mw = (wid >> 2) * 64;     // warp M offset
    const int nw = (wid & 3) * 32;      // warp N offset
    const int gr = lane >> 2;
    const int tg = lane & 3;

    // ldmatrix lane->row/k mapping (precomputed, stage-relative)
    // A x4 per fm: lanes 0-15 rows 0..15 (k lo8), lanes 16-31 same rows (k hi8)
    uint32_t aRowOff[4], aRw[4];
    const int aKc = lane >> 4;          // chunk offset within k16 step
#pragma unroll
    for (int fm = 0; fm < 4; fm++) {
        const int r = mw + fm * 16 + (lane & 15);
        aRowOff[fm] = (uint32_t)r * 128;
        aRw[fm] = (uint32_t)(r & 7);
    }
    // B x4 per pair: lanes {0-7,8-15} n-block0 (k lo/hi), {16-23,24-31} n-block1
    uint32_t bRowOff[2], bRw[2];
    const int bKc = (lane >> 3) & 1;
#pragma unroll
    for (int pr = 0; pr < 2; pr++) {
        const int r = nw + pr * 16 + ((lane >> 4) << 3) + (lane & 7);
        bRowOff[pr] = (uint32_t)r * 128;
        bRw[pr] = (uint32_t)(r & 7);
    }

    float acc[4][4][4];
#pragma unroll
    for (int i = 0; i < 4; i++)
#pragma unroll
        for (int j = 0; j < 4; j++)
#pragma unroll
            for (int q = 0; q < 4; q++) acc[i][j][q] = 0.f;

    for (int kt = 0; kt < NITER; kt++) {
        CP_WAIT1();
        __syncthreads();

        const int next = kt + STAGES - 1;
        if (next < NITER) load_stage(next % STAGES, next);
        CP_COMMIT();

        const uint32_t sA = smem_b + (kt % STAGES) * STG_B;
        const uint32_t sB = sA + A_STG_B;

#pragma unroll
        for (int ks = 0; ks < 4; ks++) {        // k16 steps within BK=64
            const int kc = ks * 2;              // base 16B-chunk index
            uint32_t a[4][4];
#pragma unroll
            for (int fm = 0; fm < 4; fm++) {
                const uint32_t addr = sA + aRowOff[fm] +
                    ((uint32_t)((kc + aKc) ^ aRw[fm]) << 4);
                LDSM_X4(a[fm][0], a[fm][1], a[fm][2], a[fm][3], addr);
            }
            uint32_t b[2][4];
#pragma unroll
            for (int pr = 0; pr < 2; pr++) {
                const uint32_t addr = sB + bRowOff[pr] +
                    ((uint32_t)((kc + bKc) ^ bRw[pr]) << 4);
                LDSM_X4(b[pr][0], b[pr][1], b[pr][2], b[pr][3], addr);
            }
#pragma unroll
            for (int fm = 0; fm < 4; fm++)
#pragma unroll
                for (int fn = 0; fn < 4; fn++)
                    mma_f16(acc[fm][fn], a[fm], &b[fn >> 1][(fn & 1) * 2]);
        }
        __syncthreads();
    }

    // ---- epilogue -----------------------------------------------------------
    const float v = g_v;
#pragma unroll
    for (int fm = 0; fm < 4; fm++) {
        const int r0 = bm + mw + fm * 16 + gr;
        const int r1 = r0 + 8;
#pragma unroll
        for (int fn = 0; fn < 4; fn++) {
            const int c = bn + nw + fn * 8 + tg * 2;
            *(float2*)&out[(size_t)r0 * N_DIM + c] =
                make_float2(v * acc[fm][fn][0], v * acc[fm][fn][1]);
            *(float2*)&out[(size_t)r1 * N_DIM + c] =
                make_float2(v * acc[fm][fn][2], v * acc[fm][fn][3]);
        }
    }
}

// ---------------------------------------------------------------------------
// Entry point
// ---------------------------------------------------------------------------
extern "C" void kernel_launch(void* const* d_in, const int* in_sizes, int n_in,
                              void* d_out, int out_size) {
    const float* x = (const float*)d_in[0];
    const float* w = (const float*)d_in[1];
    float* out = (float*)d_out;

    zero_sums_kernel<<<1, 4>>>();
    prune_kernel<<<2048, 256>>>(x);
    wconv_kernel<<<(N_DIM * K_DIM / 4) / 256, 256>>>(w);
    compute_v_kernel<<<1, 1>>>();

    cudaFuncSetAttribute(gemm_f16_kernel,
                         cudaFuncAttributeMaxDynamicSharedMemorySize, SMEM_DYN);
    dim3 grid(N_DIM / BN, M_DIM / BM);
    gemm_f16_kernel<<<grid, 256, SMEM_DYN>>>(out);
}

// round 5
// speedup vs baseline: 14.9121x; 1.1485x over previous
#include <cuda_runtime.h>
#include <cuda_fp16.h>
#include <math.h>
#include <stdint.h>

// Problem dims (fixed by setup_inputs): x [4,4096,2048] fp32, W [2048,2048] fp32
#define M_DIM 16384
#define K_DIM 2048
#define N_DIM 2048

static const long long NELEM = (long long)M_DIM * (long long)K_DIM;

// Scratch (no alloc allowed)
__device__ __half g_xsp_c[M_DIM * K_DIM / 2];          // compressed 2:4 A (32 MB)
__device__ uint16_t g_meta[M_DIM * K_DIM / 16];        // 2-bit metadata (4 MB)
__device__ __half g_wh[N_DIM * K_DIM];                 // W in fp16 (8 MB)
__device__ double g_sums[4];
__device__ float g_v;

// ---------------------------------------------------------------------------
// Kernel 0: reset accumulators
// ---------------------------------------------------------------------------
__global__ void zero_sums_kernel() {
    if (threadIdx.x < 4) g_sums[threadIdx.x] = 0.0;
}

// ---------------------------------------------------------------------------
// Kernel 1: 2:4 prune -> compressed values + metadata + moment accumulation.
// Each thread handles 16 consecutive elements (4 groups of 4).
// ---------------------------------------------------------------------------
__global__ void prune_kernel(const float* __restrict__ x) {
    const long long nb = NELEM / 16;
    float s0 = 0.f, s1 = 0.f, s2 = 0.f, s3 = 0.f;

    const long long stride = (long long)gridDim.x * blockDim.x;
    for (long long b = (long long)blockIdx.x * blockDim.x + threadIdx.x;
         b < nb; b += stride) {
        const float4* xp = (const float4*)x + b * 4;
        uint32_t packed[4];
        uint32_t meta = 0;
#pragma unroll
        for (int g = 0; g < 4; g++) {
            float4 v = xp[g];
            float e[4] = {v.x, v.y, v.z, v.w};
            float a[4] = {fabsf(v.x), fabsf(v.y), fabsf(v.z), fabsf(v.w)};
            int k0 = -1, k1 = -1;
#pragma unroll
            for (int i = 0; i < 4; i++) {
                int beats = 0;
#pragma unroll
                for (int j = 0; j < 4; j++) {
                    if (j == i) continue;
                    beats += (a[j] > a[i]) || (a[j] == a[i] && j < i);
                }
                if (beats < 2) { if (k0 < 0) k0 = i; else k1 = i; }
            }
            const float v0 = e[k0], v1 = e[k1];
            s0 += e[0] + e[1] + e[2] + e[3];
            s1 += e[0]*e[0] + e[1]*e[1] + e[2]*e[2] + e[3]*e[3];
            s2 += v0 + v1;
            s3 += v0 * v0 + v1 * v1;
            __half2 h = __floats2half2_rn(v0, v1);
            packed[g] = *(uint32_t*)&h;
            meta |= (uint32_t)(k0 | (k1 << 2)) << (4 * g);
        }
        ((uint4*)g_xsp_c)[b] = make_uint4(packed[0], packed[1], packed[2], packed[3]);
        g_meta[b] = (uint16_t)meta;
    }

#pragma unroll
    for (int off = 16; off > 0; off >>= 1) {
        s0 += __shfl_down_sync(0xffffffffu, s0, off);
        s1 += __shfl_down_sync(0xffffffffu, s1, off);
        s2 += __shfl_down_sync(0xffffffffu, s2, off);
        s3 += __shfl_down_sync(0xffffffffu, s3, off);
    }
    __shared__ float red[4][8];
    int lane = threadIdx.x & 31;
    int w = threadIdx.x >> 5;
    if (lane == 0) {
        red[0][w] = s0; red[1][w] = s1; red[2][w] = s2; red[3][w] = s3;
    }
    __syncthreads();
    if (threadIdx.x == 0) {
        float t0 = 0.f, t1 = 0.f, t2 = 0.f, t3 = 0.f;
        int nw = (blockDim.x + 31) >> 5;
        for (int i = 0; i < nw; i++) {
            t0 += red[0][i]; t1 += red[1][i]; t2 += red[2][i]; t3 += red[3][i];
        }
        atomicAdd(&g_sums[0], (double)t0);
        atomicAdd(&g_sums[1], (double)t1);
        atomicAdd(&g_sums[2], (double)t2);
        atomicAdd(&g_sums[3], (double)t3);
    }
}

// ---------------------------------------------------------------------------
// Kernel 1b: convert W to fp16
// ---------------------------------------------------------------------------
__global__ void wconv_kernel(const float* __restrict__ W) {
    const int i = blockIdx.x * blockDim.x + threadIdx.x;  // over NK/4
    float4 w4 = ((const float4*)W)[i];
    __half2* y = (__half2*)g_wh;
    y[2 * i]     = __floats2half2_rn(w4.x, w4.y);
    y[2 * i + 1] = __floats2half2_rn(w4.z, w4.w);
}

// ---------------------------------------------------------------------------
// Kernel 2: v = sqrt(var(x) / max(var(x_sp), 1e-9)), ddof=1
// ---------------------------------------------------------------------------
__global__ void compute_v_kernel() {
    double n = (double)NELEM;
    double var_x  = (g_sums[1] - g_sums[0] * g_sums[0] / n) / (n - 1.0);
    double var_sp = (g_sums[3] - g_sums[2] * g_sums[2] / n) / (n - 1.0);
    double denom = var_sp > 1e-9 ? var_sp : 1e-9;
    g_v = (float)sqrt(var_x / denom);
}

// ---------------------------------------------------------------------------
// Kernel 3: sparse fp16 GEMM  out[m][n] = v * sum_k x_sp[m][k] * W[n][k]
// mma.sp::ordered_metadata.m16n8k32. BM=BN=128, BK=128 (source K) per tile.
// Double-buffered cp.async. 8 warps (2x4), warp tile 64x32.
// ---------------------------------------------------------------------------
#define BM 128
#define BN 128
#define BKS 128                        // source K per tile
#define NITER (K_DIM / BKS)            // 16

#define A_STG_B (BM * 128)             // compressed A: 128B/row -> 16 KB
#define B_STG_B (BN * 256)             // dense B: 256B/row -> 32 KB
#define M_STG_B (BM * 16)              // meta: 16B/row -> 2 KB
#define STG_B (A_STG_B + B_STG_B + M_STG_B)   // 51200
#define SMEM_DYN (2 * STG_B + 1024)

static __device__ __forceinline__ uint32_t smem_u32(const void* p) {
    uint32_t a;
    asm("{ .reg .u64 t; cvta.to.shared.u64 t, %1; cvt.u32.u64 %0, t; }" : "=r"(a) : "l"(p));
    return a;
}

#define CP_ASYNC16(dst, src) \
    asm volatile("cp.async.cg.shared.global [%0], [%1], 16;" :: "r"(dst), "l"(src) : "memory")
#define CP_COMMIT() asm volatile("cp.async.commit_group;" ::: "memory")
#define CP_WAIT1()  asm volatile("cp.async.wait_group 1;" ::: "memory")
#define CP_WAIT0()  asm volatile("cp.async.wait_group 0;" ::: "memory")

#define LDSM_X4(r0, r1, r2, r3, addr) \
    asm volatile("ldmatrix.sync.aligned.m8n8.x4.shared.b16 {%0,%1,%2,%3}, [%4];" \
        : "=r"(r0), "=r"(r1), "=r"(r2), "=r"(r3) : "r"(addr))

static __device__ __forceinline__ void mma_sp(
    float* c, const uint32_t* a,
    uint32_t b0, uint32_t b1, uint32_t b2, uint32_t b3, uint32_t e) {
    asm volatile(
        "mma.sp::ordered_metadata.sync.aligned.m16n8k32.row.col.f32.f16.f16.f32 "
        "{%0,%1,%2,%3}, {%4,%5,%6,%7}, {%8,%9,%10,%11}, {%0,%1,%2,%3}, %12, 0x0;"
        : "+f"(c[0]), "+f"(c[1]), "+f"(c[2]), "+f"(c[3])
        : "r"(a[0]), "r"(a[1]), "r"(a[2]), "r"(a[3]),
          "r"(b0), "r"(b1), "r"(b2), "r"(b3), "r"(e));
}

__global__ __launch_bounds__(256, 2)
void gemm_sp_kernel(float* __restrict__ out) {
    extern __shared__ char smem[];

    const int tid = threadIdx.x;
    const int wid = tid >> 5;
    const int lane = tid & 31;
    const int bm = blockIdx.y * BM;
    const int bn = blockIdx.x * BN;

    const uint32_t tile_base = (smem_u32(smem) + 1023u) & ~1023u;
    const char* a_gm = (const char*)g_xsp_c + (size_t)bm * (K_DIM / 2 * 2);  // 2048B/row
    const char* b_gm = (const char*)g_wh + (size_t)bn * (K_DIM * 2);         // 4096B/row
    const char* m_gm = (const char*)g_meta + (size_t)bm * (K_DIM / 16 * 2);  // 256B/row

    // ---- async loader: stage buf <- ktile kt --------------------------------
    auto load_stage = [&](int buf, int kt) {
        const uint32_t sA = tile_base + buf * STG_B;
        const uint32_t sB = sA + A_STG_B;
        const uint32_t sM = sB + B_STG_B;
        // A compressed: 128 rows x 128B, SW128 (chunk ^ row&7)
        const int ka = kt * 128;
#pragma unroll
        for (int i = 0; i < 4; i++) {
            const int ch = tid + i * 256;      // 0..1023
            const int row = ch >> 3, c = ch & 7;
            CP_ASYNC16(sA + row * 128 + ((uint32_t)(c ^ (row & 7)) << 4),
                       a_gm + (size_t)row * 2048 + ka + c * 16);
        }
        // B dense: 128 rows x 256B, swizzle low-3 of chunk
        const int kb = kt * 256;
#pragma unroll
        for (int i = 0; i < 8; i++) {
            const int ch = tid + i * 256;      // 0..2047
            const int row = ch >> 4, c = ch & 15;
            const uint32_t swc = (uint32_t)((c & 8) | ((c ^ row) & 7));
            CP_ASYNC16(sB + row * 256 + (swc << 4),
                       b_gm + (size_t)row * 4096 + kb + c * 16);
        }
        // meta: 128 rows x 16B
        if (tid < 128) {
            CP_ASYNC16(sM + tid * 16, m_gm + (size_t)tid * 256 + kt * 16);
        }
    };

    load_stage(0, 0);
    CP_COMMIT();

    const int mw = (wid >> 2) * 64;     // warp M offset
    const int nw = (wid & 3) * 32;      // warp N offset
    const int gr = lane >> 2;
    const int tg = lane & 3;

    float acc[4][4][4];
#pragma unroll
    for (int i = 0; i < 4; i++)
#pragma unroll
        for (int j = 0; j < 4; j++)
#pragma unroll
            for (int q = 0; q < 4; q++) acc[i][j][q] = 0.f;

    // precomputed fragment addressing
    const int aRow = lane & 15;                 // within 16-row block
    const int aKc = lane >> 4;                  // chunk parity
    const int bRow = ((lane >> 4) << 3) + (lane & 7);
    const int bKc = (lane >> 3) & 1;
    const int eQ = lane & 1;                    // metadata half selector

    for (int kt = 0; kt < NITER; kt++) {
        if (kt + 1 < NITER) {
            load_stage((kt + 1) & 1, kt + 1);
            CP_COMMIT();
            CP_WAIT1();
        } else {
            CP_WAIT0();
        }
        __syncthreads();

        const uint32_t sA = tile_base + (kt & 1) * STG_B;
        const uint32_t sB = sA + A_STG_B;
        const uint32_t sM = sB + B_STG_B;

#pragma unroll
        for (int s = 0; s < 4; s++) {           // 4 x k32 steps (compressed k16)
            uint32_t a[4][4];
#pragma unroll
            for (int fm = 0; fm < 4; fm++) {
                const int row = mw + fm * 16 + aRow;
                const int c = s * 2 + aKc;
                LDSM_X4(a[fm][0], a[fm][1], a[fm][2], a[fm][3],
                        sA + row * 128 + ((uint32_t)(c ^ (row & 7)) << 4));
            }
            uint32_t bf[2][2][4];               // [pr][khalf][reg]
#pragma unroll
            for (int pr = 0; pr < 2; pr++)
#pragma unroll
                for (int h = 0; h < 2; h++) {
                    const int row = nw + pr * 16 + bRow;
                    const int c = s * 4 + h * 2 + bKc;
                    const uint32_t swc = (uint32_t)((c & 8) | ((c ^ row) & 7));
                    LDSM_X4(bf[pr][h][0], bf[pr][h][1], bf[pr][h][2], bf[pr][h][3],
                            sB + row * 256 + (swc << 4));
                }
            uint32_t ee[4];
#pragma unroll
            for (int fm = 0; fm < 4; fm++) {
                const int r = mw + fm * 16 + gr;
                const uint32_t ma = sM + r * 16 + (s * 2 + eQ) * 2;
                uint32_t lo, hi;
                asm volatile("ld.shared.u16 %0, [%1];" : "=r"(lo) : "r"(ma));
                asm volatile("ld.shared.u16 %0, [%1];" : "=r"(hi) : "r"(ma + 128));
                ee[fm] = lo | (hi << 16);
            }
#pragma unroll
            for (int fm = 0; fm < 4; fm++)
#pragma unroll
                for (int fn = 0; fn < 4; fn++)
                    mma_sp(acc[fm][fn], a[fm],
                           bf[fn >> 1][0][(fn & 1) * 2], bf[fn >> 1][0][(fn & 1) * 2 + 1],
                           bf[fn >> 1][1][(fn & 1) * 2], bf[fn >> 1][1][(fn & 1) * 2 + 1],
                           ee[fm]);
        }
        __syncthreads();
    }

    // ---- epilogue -----------------------------------------------------------
    const float v = g_v;
#pragma unroll
    for (int fm = 0; fm < 4; fm++) {
        const int r0 = bm + mw + fm * 16 + gr;
        const int r1 = r0 + 8;
#pragma unroll
        for (int fn = 0; fn < 4; fn++) {
            const int c = bn + nw + fn * 8 + tg * 2;
            *(float2*)&out[(size_t)r0 * N_DIM + c] =
                make_float2(v * acc[fm][fn][0], v * acc[fm][fn][1]);
            *(float2*)&out[(size_t)r1 * N_DIM + c] =
                make_float2(v * acc[fm][fn][2], v * acc[fm][fn][3]);
        }
    }
}

// ---------------------------------------------------------------------------
// Entry point
// ---------------------------------------------------------------------------
extern "C" void kernel_launch(void* const* d_in, const int* in_sizes, int n_in,
                              void* d_out, int out_size) {
    const float* x = (const float*)d_in[0];
    const float* w = (const float*)d_in[1];
    float* out = (float*)d_out;

    zero_sums_kernel<<<1, 4>>>();
    prune_kernel<<<2048, 256>>>(x);
    wconv_kernel<<<(N_DIM * K_DIM / 4) / 256, 256>>>(w);
    compute_v_kernel<<<1, 1>>>();

    cudaFuncSetAttribute(gemm_sp_kernel,
                         cudaFuncAttributeMaxDynamicSharedMemorySize, SMEM_DYN);
    dim3 grid(N_DIM / BN, M_DIM / BM);
    gemm_sp_kernel<<<grid, 256, SMEM_DYN>>>(out);
}